// round 7
// baseline (speedup 1.0000x reference)
#include <cuda_runtime.h>

// FFJORD: 2 chained fixed-step DOPRI5 integrations of a (64+1)->256->256->64 MLP.
// One CTA integrates 16 batch rows. fp32 via fma.rn.f32x2, zero-MOV operands.
// R7: split-K across 8 warps (NT=256): warps 0-3 do k<K/2, warps 4-7 do k>=K/2
// on identical 8rowx4col tiles; kg1 stores f32x2 partials to smem, kg0 reduces
// with add.rn.f32x2. 2048 warps total -> ~14 warps/SM latency cover.

typedef unsigned long long u64;

#define Dd     64
#define Hh     256
#define MROWS  16
#define STRD   36      // duplicated-activation stride (floats)
#define STRH2  20      // non-dup H2 stride (floats)
#define STRY   16
#define NT     256
#define NSTEPS 16
#define NCTAS  (4096 / MROWS)   // 256
#define RD     4       // weight prefetch ring depth

// smem: sZd[(Dd+1)][STRD] + sH1d[Hh][STRD] + sH2[Hh][STRH2] + sY[Dd][STRY]
//       + sPart[128 threads][8 ulonglong2]
#define SM_FLOATS ((Dd + 1 + Hh) * STRD + Hh * STRH2 + Dd * STRY)
#define SM_BYTES  (SM_FLOATS * 4 + 128 * 8 * 16)   // 70800 + 16384 = 87184

__device__ float gK[NCTAS][6 * Dd * STRY];

struct FfjordParams {
    const float* W1[2]; const float* b1[2];
    const float* W2[2]; const float* b2[2];
    const float* W3[2]; const float* b3[2];
};

__device__ __forceinline__ u64 mk2(float lo, float hi) {
    u64 r; asm("mov.b64 %0, {%1, %2};" : "=l"(r)
               : "r"(__float_as_uint(lo)), "r"(__float_as_uint(hi)));
    return r;
}
__device__ __forceinline__ u64 dup2(float v) {
    u64 r; asm("mov.b64 %0, {%1, %1};" : "=l"(r) : "r"(__float_as_uint(v)));
    return r;
}
__device__ __forceinline__ void fma2(u64& d, u64 a, u64 b) {
    asm("fma.rn.f32x2 %0, %1, %2, %3;" : "=l"(d) : "l"(a), "l"(b), "l"(d));
}
__device__ __forceinline__ u64 add2(u64 a, u64 b) {
    u64 r; asm("add.rn.f32x2 %0, %1, %2;" : "=l"(r) : "l"(a), "l"(b)); return r;
}
__device__ __forceinline__ float lo32(u64 v){ return __uint_as_float((unsigned)v); }
__device__ __forceinline__ float hi32(u64 v){ return __uint_as_float((unsigned)(v>>32)); }

__device__ __forceinline__ void ldg2(u64& a, u64& b, const float* p) {
    asm("ld.global.nc.v2.u64 {%0, %1}, [%2];" : "=l"(a), "=l"(b) : "l"(p));
}
__device__ __forceinline__ u64 ldg1(const float* p) {
    u64 r; asm("ld.global.nc.u64 %0, [%1];" : "=l"(r) : "l"(p)); return r;
}

__device__ __forceinline__ float fast_tanh(float x) {
    float u = __expf(2.0f * x);
    return 1.0f - __fdividef(2.0f, u + 1.0f);
}

__constant__ float DP_A[6][5] = {
    { 0.f, 0.f, 0.f, 0.f, 0.f },
    { 1.f/5.f, 0.f, 0.f, 0.f, 0.f },
    { 3.f/40.f, 9.f/40.f, 0.f, 0.f, 0.f },
    { 44.f/45.f, -56.f/15.f, 32.f/9.f, 0.f, 0.f },
    { 19372.f/6561.f, -25360.f/2187.f, 64448.f/6561.f, -212.f/729.f, 0.f },
    { 9017.f/3168.f, -355.f/33.f, 46732.f/5247.f, 49.f/176.f, -5103.f/18656.f },
};
__constant__ float DP_C[6] = { 0.f, 1.f/5.f, 3.f/10.f, 4.f/5.f, 8.f/9.f, 1.f };

// N=256 layer, split-K over 8 warps. Warp w: w4=w&3 -> rowgroup rg=w4&1
// (rows 8*rg..+7), colgroup g=w4>>1 (cols 128*g+4*lane..+3); kg=w>>2 picks
// k in [kbeg,kend). kg1 stores partials; kg0 reduces + activation + store.
template<bool TANH, bool DUPOUT>
__device__ __forceinline__ void dense256_split(
    const float* __restrict__ W, const float* __restrict__ bias,
    const float* __restrict__ sAd, float* __restrict__ sOut,
    ulonglong2* __restrict__ sPart,
    int lane, int g, int r0, int kg, int kbeg, int kend, int t128)
{
    u64 acc[8][2];
    if (kg == 0) {
        float4 b = *(const float4*)(bias + 128*g + 4*lane);
        u64 p0 = mk2(b.x, b.y), p1 = mk2(b.z, b.w);
#pragma unroll
        for (int r = 0; r < 8; r++) { acc[r][0] = p0; acc[r][1] = p1; }
    } else {
#pragma unroll
        for (int r = 0; r < 8; r++) { acc[r][0] = 0ull; acc[r][1] = 0ull; }
    }

    const int cnt = kend - kbeg;
    const float* w0 = W + kbeg*Hh + 128*g + 4*lane;
    const float* aP = sAd + kbeg*STRD + 2*r0;

    u64 wb[RD][2];
#pragma unroll
    for (int s = 0; s < RD; s++) ldg2(wb[s][0], wb[s][1], w0 + s*Hh);

    u64 ab[2][8];
#pragma unroll
    for (int q = 0; q < 4; q++) {
        ulonglong2 t = *(const ulonglong2*)(aP + 4*q);
        ab[0][2*q] = t.x; ab[0][2*q+1] = t.y;
    }

    int k = 0;
#pragma unroll 4
    for (; k < cnt - RD; k++) {
        const int slot = k & (RD-1), pb = k & 1;
        u64 wA = wb[slot][0], wB = wb[slot][1];
        ldg2(wb[slot][0], wb[slot][1], w0 + (k + RD)*Hh);
        {
            const float* ap1 = aP + (k+1)*STRD;
#pragma unroll
            for (int q = 0; q < 4; q++) {
                ulonglong2 t = *(const ulonglong2*)(ap1 + 4*q);
                ab[pb^1][2*q] = t.x; ab[pb^1][2*q+1] = t.y;
            }
        }
#pragma unroll
        for (int r = 0; r < 8; r++) {
            fma2(acc[r][0], ab[pb][r], wA);
            fma2(acc[r][1], ab[pb][r], wB);
        }
    }
    for (; k < cnt; k++) {
        const int slot = k & (RD-1), pb = k & 1;
        u64 wA = wb[slot][0], wB = wb[slot][1];
        if (k + 1 < cnt) {
            const float* ap1 = aP + (k+1)*STRD;
#pragma unroll
            for (int q = 0; q < 4; q++) {
                ulonglong2 t = *(const ulonglong2*)(ap1 + 4*q);
                ab[pb^1][2*q] = t.x; ab[pb^1][2*q+1] = t.y;
            }
        }
#pragma unroll
        for (int r = 0; r < 8; r++) {
            fma2(acc[r][0], ab[pb][r], wA);
            fma2(acc[r][1], ab[pb][r], wB);
        }
    }

    // split-K reduction
    if (kg) {
#pragma unroll
        for (int r = 0; r < 8; r++)
            sPart[r*128 + t128] = make_ulonglong2(acc[r][0], acc[r][1]);
    }
    __syncthreads();
    if (!kg) {
#pragma unroll
        for (int r = 0; r < 8; r++) {
            ulonglong2 pp = sPart[r*128 + t128];
            acc[r][0] = add2(acc[r][0], pp.x);
            acc[r][1] = add2(acc[r][1], pp.y);
        }
#pragma unroll
        for (int p = 0; p < 2; p++) {
            int c = 128*g + 4*lane + 2*p;
            float lv[8], hv[8];
#pragma unroll
            for (int r = 0; r < 8; r++) {
                lv[r] = lo32(acc[r][p]); hv[r] = hi32(acc[r][p]);
                if (TANH) { lv[r] = fast_tanh(lv[r]); hv[r] = fast_tanh(hv[r]); }
            }
            if (DUPOUT) {
                float* o0 = sOut + c*STRD + 2*r0;
                float* o1 = sOut + (c+1)*STRD + 2*r0;
#pragma unroll
                for (int q = 0; q < 4; q++) {
                    *(float4*)(o0 + 4*q) = make_float4(lv[2*q], lv[2*q], lv[2*q+1], lv[2*q+1]);
                    *(float4*)(o1 + 4*q) = make_float4(hv[2*q], hv[2*q], hv[2*q+1], hv[2*q+1]);
                }
            } else {
                float* o0 = sOut + c*STRH2 + r0;
                float* o1 = sOut + (c+1)*STRH2 + r0;
                *(float4*)(o0)     = make_float4(lv[0], lv[1], lv[2], lv[3]);
                *(float4*)(o0 + 4) = make_float4(lv[4], lv[5], lv[6], lv[7]);
                *(float4*)(o1)     = make_float4(hv[0], hv[1], hv[2], hv[3]);
                *(float4*)(o1 + 4) = make_float4(hv[4], hv[5], hv[6], hv[7]);
            }
        }
    }
}

// N=64 output layer, split-K. Warp w4 -> rows 4*w4..+3; thread cols
// (2*lane, 2*lane+1); kg halves of K=256. Reads non-dup H2.
__device__ __forceinline__ void dense64_split(
    const float* __restrict__ W, const float* __restrict__ bias,
    const float* __restrict__ sA, float* __restrict__ gOut,
    ulonglong2* __restrict__ sPart,
    int lane, int r0d, int kg, int t128)
{
    u64 acc[4];
    if (kg == 0) {
        float2 bb = *(const float2*)(bias + 2*lane);
        u64 bp = mk2(bb.x, bb.y);
#pragma unroll
        for (int r = 0; r < 4; r++) acc[r] = bp;
    } else {
#pragma unroll
        for (int r = 0; r < 4; r++) acc[r] = 0ull;
    }
    const int kbeg = kg * (Hh/2), cnt = Hh/2;
    const float* w0 = W + kbeg*Dd + 2*lane;
    const float* aP = sA + kbeg*STRH2 + r0d;

    u64 wb[RD];
#pragma unroll
    for (int s = 0; s < RD; s++) wb[s] = ldg1(w0 + s*Dd);
    float4 af[2];
    af[0] = *(const float4*)(aP);

    int k = 0;
#pragma unroll 4
    for (; k < cnt - RD; k++) {
        const int slot = k & (RD-1), pb = k & 1;
        u64 w = wb[slot];
        wb[slot] = ldg1(w0 + (k + RD)*Dd);
        float4 a4 = af[pb];
        af[pb^1] = *(const float4*)(aP + (k+1)*STRH2);
        fma2(acc[0], dup2(a4.x), w); fma2(acc[1], dup2(a4.y), w);
        fma2(acc[2], dup2(a4.z), w); fma2(acc[3], dup2(a4.w), w);
    }
    for (; k < cnt; k++) {
        const int slot = k & (RD-1), pb = k & 1;
        u64 w = wb[slot];
        float4 a4 = af[pb];
        if (k + 1 < cnt) af[pb^1] = *(const float4*)(aP + (k+1)*STRH2);
        fma2(acc[0], dup2(a4.x), w); fma2(acc[1], dup2(a4.y), w);
        fma2(acc[2], dup2(a4.z), w); fma2(acc[3], dup2(a4.w), w);
    }

    if (kg) {
        sPart[t128]       = make_ulonglong2(acc[0], acc[1]);
        sPart[128 + t128] = make_ulonglong2(acc[2], acc[3]);
    }
    __syncthreads();
    if (!kg) {
        ulonglong2 p0 = sPart[t128], p1 = sPart[128 + t128];
        acc[0] = add2(acc[0], p0.x); acc[1] = add2(acc[1], p0.y);
        acc[2] = add2(acc[2], p1.x); acc[3] = add2(acc[3], p1.y);
        *(float4*)(gOut + (2*lane    )*STRY + r0d) =
            make_float4(lo32(acc[0]), lo32(acc[1]), lo32(acc[2]), lo32(acc[3]));
        *(float4*)(gOut + (2*lane + 1)*STRY + r0d) =
            make_float4(hi32(acc[0]), hi32(acc[1]), hi32(acc[2]), hi32(acc[3]));
    }
}

__global__ void __launch_bounds__(NT, 2)
ffjord_kernel(const float* __restrict__ x, float* __restrict__ out, FfjordParams P)
{
    extern __shared__ float sm[];
    float* sZd  = sm;                          // (Dd+1) x STRD, duplicated
    float* sH1d = sZd + (Dd + 1) * STRD;       // Hh x STRD, duplicated
    float* sH2  = sH1d + Hh * STRD;            // Hh x STRH2, plain
    float* sY   = sH2 + Hh * STRH2;            // Dd x STRY
    ulonglong2* sPart = (ulonglong2*)(sY + Dd * STRY);  // 128 x 8 ulonglong2

    const int tid   = threadIdx.x;
    const int lane  = tid & 31;
    const int w     = tid >> 5;                // 0..7
    const int w4    = w & 3;
    const int kg    = w >> 2;                  // split-K group
    const int r0    = (w4 & 1) * 8;            // dense256 rowgroup (8 rows)
    const int g     = w4 >> 1;                 // dense256 colgroup
    const int r0d   = w4 * 4;                  // dense64 rowgroup (4 rows)
    const int t128  = tid & 127;
    const int rbase = blockIdx.x * MROWS;
    float* gk = gK[blockIdx.x];

    for (int i = tid; i < MROWS * Dd; i += NT) {
        int r = i >> 6, d = i & 63;
        sY[d * STRY + r] = x[(rbase + r) * Dd + d];
    }
    __syncthreads();

    const float h = 1.0f / 16.0f;

    for (int bij = 0; bij < 2; bij++) {
        const float* W1 = P.W1[bij]; const float* b1 = P.b1[bij];
        const float* W2 = P.W2[bij]; const float* b2 = P.b2[bij];
        const float* W3 = P.W3[bij]; const float* b3 = P.b3[bij];

        for (int step = 0; step < NSTEPS; step++) {
            float t0 = (float)step * h;

            for (int s = 0; s < 6; s++) {
                float tstage = t0 + DP_C[s] * h;
                float ha[5];
#pragma unroll
                for (int l = 0; l < 5; l++) ha[l] = h * DP_A[s][l];

                for (int i = tid; i < (Dd + 1) * MROWS; i += NT) {
                    int d = i >> 4, r = i & 15;
                    float z;
                    if (d == Dd) {
                        z = tstage;
                    } else {
                        z = sY[d * STRY + r];
#pragma unroll
                        for (int l = 0; l < 5; l++)
                            if (l < s) z += ha[l] * gk[(l * Dd + d) * STRY + r];
                    }
                    *(float2*)(sZd + d * STRD + 2 * r) = make_float2(z, z);
                }
                __syncthreads();

                // layer 1: K=65 -> kg0 [0,33), kg1 [33,65)
                dense256_split<true, true >(W1, b1, sZd,  sH1d, sPart,
                    lane, g, r0, kg, kg ? 33 : 0, kg ? 65 : 33, t128);
                __syncthreads();
                // layer 2: K=256 -> halves
                dense256_split<true, false>(W2, b2, sH1d, sH2,  sPart,
                    lane, g, r0, kg, kg ? 128 : 0, kg ? 256 : 128, t128);
                __syncthreads();
                dense64_split(W3, b3, sH2, gk + s * Dd * STRY, sPart,
                    lane, r0d, kg, t128);
                __syncthreads();
            }

            for (int i = tid; i < Dd * MROWS; i += NT) {
                int d = i >> 4, r = i & 15;
                int o = d * STRY + r;
                float acc = (35.f/384.f)     * gk[o]
                          + (500.f/1113.f)   * gk[(2*Dd)*STRY + o]
                          + (125.f/192.f)    * gk[(3*Dd)*STRY + o]
                          + (-2187.f/6784.f) * gk[(4*Dd)*STRY + o]
                          + (11.f/84.f)      * gk[(5*Dd)*STRY + o];
                sY[o] += h * acc;
            }
            __syncthreads();
        }
    }

    for (int i = tid; i < MROWS * Dd; i += NT) {
        int r = i >> 6, d = i & 63;
        out[(rbase + r) * Dd + d] = sY[d * STRY + r];
    }
}

extern "C" void kernel_launch(void* const* d_in, const int* in_sizes, int n_in,
                              void* d_out, int out_size)
{
    (void)in_sizes; (void)n_in; (void)out_size;
    const float* x = (const float*)d_in[0];

    FfjordParams P;
    P.W1[0] = (const float*)d_in[1];  P.b1[0] = (const float*)d_in[2];
    P.W2[0] = (const float*)d_in[3];  P.b2[0] = (const float*)d_in[4];
    P.W3[0] = (const float*)d_in[5];  P.b3[0] = (const float*)d_in[6];
    P.W1[1] = (const float*)d_in[7];  P.b1[1] = (const float*)d_in[8];
    P.W2[1] = (const float*)d_in[9];  P.b2[1] = (const float*)d_in[10];
    P.W3[1] = (const float*)d_in[11]; P.b3[1] = (const float*)d_in[12];

    static_assert(SM_BYTES <= 100 * 1024, "smem budget (2 CTAs/SM)");
    cudaFuncSetAttribute(ffjord_kernel, cudaFuncAttributeMaxDynamicSharedMemorySize, SM_BYTES);

    ffjord_kernel<<<NCTAS, NT, SM_BYTES>>>(x, (float*)d_out, P);
}